// round 8
// baseline (speedup 1.0000x reference)
#include <cuda_runtime.h>
#include <cuda_bf16.h>
#include <math.h>

// ContrastiveLoss: N=8192 points, D=64, labels int32 in [0,8).
// loss = [ sum_{same-label,i!=j} d2  +  sum_{diff-label} max(1-d,0)^2 ] / (N*(N-1))
//
//   pos term: exact closed form per class: sum d2 = 2*(n_c*S2_c - |S1_c|^2)  (O(N*D))
//   neg term: nonzero only when d < 1. 8-dim partial distance (dot form) is an exact
//             lower bound on d2 -> screen all pairs, branch-coarsened rare path
//             evaluates survivors exactly on all 64 dims.
// Accumulators are zero at module load and re-zeroed by finalize after each use,
// so no zero kernel is needed and every graph replay starts clean.

#define N_PTS 8192
#define NDIM  64
#define NCLS  8
#define TI    512     // i-rows per screen block (4 per thread)
#define TJ    128     // j-rows per screen block

__device__ float  g_s1[NCLS * NDIM];   // per-class vector sums (RED.ADD targets)
__device__ float  g_s2[NCLS * NDIM];   // per-class per-dim sum of squares
__device__ int    g_hist[NCLS];        // class histogram
__device__ double g_neg;

// ---------------- K1: prep (per-class sums + histogram, smem-reduced) ---------
// grid 128 x 256 threads. Block b: rows [b*64, b*64+64).
// Thread t: k = t&63 (dim), g = t>>6 (row group of 16).
__global__ void __launch_bounds__(256) prep_kernel(const float* __restrict__ X,
                                                   const int* __restrict__ lab) {
    int t  = threadIdx.x;
    int k  = t & 63;
    int g  = t >> 6;
    int r0 = blockIdx.x * 64 + g * 16;

    __shared__ int   slab[64];
    __shared__ float red1[4][NCLS * NDIM];
    __shared__ float red2[4][NCLS * NDIM];
    if (t < 64) slab[t] = lab[blockIdx.x * 64 + t];
    __syncthreads();

    float a1[NCLS], a2[NCLS];
#pragma unroll
    for (int c = 0; c < NCLS; c++) { a1[c] = 0.0f; a2[c] = 0.0f; }
#pragma unroll
    for (int rr = 0; rr < 16; ++rr) {
        float v  = X[(r0 + rr) * NDIM + k];
        float v2 = v * v;
        int   c  = slab[g * 16 + rr];
#pragma unroll
        for (int cc = 0; cc < NCLS; cc++) {
            bool m = (cc == c);
            a1[cc] += m ? v  : 0.0f;
            a2[cc] += m ? v2 : 0.0f;
        }
    }
#pragma unroll
    for (int cc = 0; cc < NCLS; cc++) {
        red1[g][cc * NDIM + k] = a1[cc];
        red2[g][cc * NDIM + k] = a2[cc];
    }
    __syncthreads();
    // 512 accumulator slots, 256 threads -> 2 slots per thread
#pragma unroll
    for (int q = 0; q < 2; q++) {
        int idx = q * 256 + t;
        float s1 = red1[0][idx] + red1[1][idx] + red1[2][idx] + red1[3][idx];
        float s2 = red2[0][idx] + red2[1][idx] + red2[2][idx] + red2[3][idx];
        atomicAdd(&g_s1[idx], s1);
        atomicAdd(&g_s2[idx], s2);
    }
    // class histogram for this block's 64 labels: thread c counts class c
    if (t < NCLS) {
        int cnt = 0;
#pragma unroll
        for (int rr = 0; rr < 64; rr++) cnt += (slab[rr] == t) ? 1 : 0;
        atomicAdd(&g_hist[t], cnt);
    }
}

// ---------------- rare path: exact 64-dim evaluation ----------------
__device__ __noinline__ void eval_pair(const float* __restrict__ X,
                                       const int* __restrict__ lab, int i, int j) {
    if (j <= i) return;                 // diagonal-region duplicates / self pair
    if (lab[i] == lab[j]) return;       // same-label handled in closed form
    const float4* xi = (const float4*)(X + i * NDIM);
    const float4* xj = (const float4*)(X + j * NDIM);
    float s = 0.0f;
#pragma unroll
    for (int q = 0; q < 16; q++) {
        float4 a = xi[q], b = xj[q];
        float d;
        d = a.x - b.x; s = fmaf(d, d, s);
        d = a.y - b.y; s = fmaf(d, d, s);
        d = a.z - b.z; s = fmaf(d, d, s);
        d = a.w - b.w; s = fmaf(d, d, s);
    }
    if (s < 1.0f) {
        float u = 1.0f - sqrtf(fmaxf(s, 0.0f));
        atomicAdd(&g_neg, 2.0 * (double)u * (double)u);   // unordered -> ordered pairs
    }
}

__device__ __forceinline__ float half_norm8(float4 v0, float4 v1) {
    float s = v0.x * v0.x;
    s = fmaf(v0.y, v0.y, s);
    s = fmaf(v0.z, v0.z, s);
    s = fmaf(v0.w, v0.w, s);
    s = fmaf(v1.x, v1.x, s);
    s = fmaf(v1.y, v1.y, s);
    s = fmaf(v1.z, v1.z, s);
    s = fmaf(v1.w, v1.w, s);
    return 0.5f * s;
}

__device__ __forceinline__ float dot8m(float4 a0, float4 a1,
                                       float4 b0, float4 b1, float mh) {
    float s = fmaf(a0.x, b0.x, mh);
    s = fmaf(a0.y, b0.y, s);
    s = fmaf(a0.z, b0.z, s);
    s = fmaf(a0.w, b0.w, s);
    s = fmaf(a1.x, b1.x, s);
    s = fmaf(a1.y, b1.y, s);
    s = fmaf(a1.z, b1.z, s);
    s = fmaf(a1.w, b1.w, s);
    return s;
}

// ---------------- K2: screen (8-dim dot-form lower bound) + inline eval -------
// grid (64, 16), 128 threads. Block (bj,bi): i in [bi*512,+512), j in [bj*128,+128).
// Keep blocks that can contain j > i pairs: bj >= 4*bi. The j>i / same-label tests
// live in the rare eval path; the hot loop is one branch region per 8 pairs.
// Pass test: dot8 - hj > hi - 0.505  <=>  partial d2 over 8 dims < 1.01 (exact LB).
__global__ void __launch_bounds__(128) screen_kernel(const float* __restrict__ X,
                                                     const int* __restrict__ lab) {
    int bi = blockIdx.y, bj = blockIdx.x;
    if (bj < 4 * bi) return;
    int t = threadIdx.x;

    __shared__ float4 sj[TJ][2];
    __shared__ float  smhj[TJ];       // -hj
    const float4* Xv = (const float4*)X;

    int jr = bj * TJ + t;
    float4 j0 = Xv[jr * 16 + 0];
    float4 j1 = Xv[jr * 16 + 1];
    sj[t][0] = j0;
    sj[t][1] = j1;
    smhj[t]  = -half_norm8(j0, j1);

    float4 a[4][2];
    float  ci[4];
    int    ib[4];
#pragma unroll
    for (int r = 0; r < 4; r++) {
        ib[r]   = bi * TI + r * 128 + t;
        a[r][0] = Xv[ib[r] * 16 + 0];
        a[r][1] = Xv[ib[r] * 16 + 1];
        ci[r]   = half_norm8(a[r][0], a[r][1]) - 0.505f;
    }
    __syncthreads();

#pragma unroll 4
    for (int j = 0; j < TJ; j += 2) {
        float4 c0 = sj[j][0],     c1 = sj[j][1];
        float4 d0 = sj[j + 1][0], d1 = sj[j + 1][1];
        float mha = smhj[j], mhb = smhj[j + 1];
        float da[4], db[4];
        bool any = false;
#pragma unroll
        for (int r = 0; r < 4; r++) {
            da[r] = dot8m(a[r][0], a[r][1], c0, c1, mha);
            db[r] = dot8m(a[r][0], a[r][1], d0, d1, mhb);
            any = any | (da[r] > ci[r]) | (db[r] > ci[r]);
        }
        if (any) {
            int jga = bj * TJ + j;
#pragma unroll
            for (int r = 0; r < 4; r++) {
                if (da[r] > ci[r]) eval_pair(X, lab, ib[r], jga);
                if (db[r] > ci[r]) eval_pair(X, lab, ib[r], jga + 1);
            }
        }
    }
}

// ---------------- K3: finalize (tiny) + reset accumulators --------------------
__global__ void __launch_bounds__(512) finalize_kernel(float* __restrict__ out) {
    int t = threadIdx.x;                    // t = c*64 + k
    __shared__ double red[512];

    int c = t >> 6;
    double S1 = (double)g_s1[t];
    double S2 = (double)g_s2[t];
    red[t] = (double)g_hist[c] * S2 - S1 * S1;
    __syncthreads();
    for (int s = 256; s > 0; s >>= 1) {
        if (t < s) red[t] += red[t + s];
        __syncthreads();
    }
    if (t == 0) {
        double pos  = 2.0 * red[0];
        double loss = (pos + g_neg) / ((double)N_PTS * (double)(N_PTS - 1));
        out[0] = (float)loss;
    }
    // reset for the next graph replay (globals are 0 at module load)
    g_s1[t] = 0.0f;
    g_s2[t] = 0.0f;
    if (t < NCLS) g_hist[t] = 0;
    if (t == 0)   g_neg = 0.0;
}

extern "C" void kernel_launch(void* const* d_in, const int* in_sizes, int n_in,
                              void* d_out, int out_size) {
    const float* X   = (const float*)d_in[0];
    const int*   lab = (const int*)d_in[1];
    float*       out = (float*)d_out;

    prep_kernel<<<128, 256>>>(X, lab);
    dim3 g(64, 16);
    screen_kernel<<<g, 128>>>(X, lab);
    finalize_kernel<<<1, 512>>>(out);
}

// round 9
// speedup vs baseline: 3.8227x; 3.8227x over previous
#include <cuda_runtime.h>
#include <cuda_bf16.h>
#include <math.h>

// ContrastiveLoss: N=8192 points, D=64, labels int32 in [0,8).
// loss = [ sum_{same-label,i!=j} d2  +  sum_{diff-label} max(1-d,0)^2 ] / (N*(N-1))
//
//   pos term: exact closed form per class: sum d2 = 2*(n_c*S2_c - |S1_c|^2)  (O(N*D))
//   neg term: nonzero only when d < 1. 8-dim partial distance (dot form) is an exact
//             lower bound on d2 -> screen all pairs; survivors are compacted into a
//             smem buffer (no calls in the hot loop) and exactly evaluated after.
//             If a block's buffer overflows (>1024 survivors in one tile; ~40x
//             margin), that block discards the buffer and re-screens its tile with
//             direct evaluation — exact for any input.
// Accumulators are zero at module load and re-zeroed by finalize after each use.

#define N_PTS 8192
#define NDIM  64
#define NCLS  8
#define TI    512     // i-rows per screen block (4 per thread)
#define TJ    128     // j-rows per screen block
#define SCAP  1024    // survivor buffer entries per block

__device__ float  g_s1[NCLS * NDIM];   // per-class vector sums (RED.ADD targets)
__device__ float  g_s2[NCLS * NDIM];   // per-class per-dim sum of squares
__device__ int    g_hist[NCLS];        // class histogram
__device__ double g_neg;

// ---------------- K1: prep (per-class sums + histogram, smem-reduced) ---------
__global__ void __launch_bounds__(256) prep_kernel(const float* __restrict__ X,
                                                   const int* __restrict__ lab) {
    int t  = threadIdx.x;
    int k  = t & 63;
    int g  = t >> 6;
    int r0 = blockIdx.x * 64 + g * 16;

    __shared__ int   slab[64];
    __shared__ float red1[4][NCLS * NDIM];
    __shared__ float red2[4][NCLS * NDIM];
    if (t < 64) slab[t] = lab[blockIdx.x * 64 + t];
    __syncthreads();

    float a1[NCLS], a2[NCLS];
#pragma unroll
    for (int c = 0; c < NCLS; c++) { a1[c] = 0.0f; a2[c] = 0.0f; }
#pragma unroll
    for (int rr = 0; rr < 16; ++rr) {
        float v  = X[(r0 + rr) * NDIM + k];
        float v2 = v * v;
        int   c  = slab[g * 16 + rr];
#pragma unroll
        for (int cc = 0; cc < NCLS; cc++) {
            bool m = (cc == c);
            a1[cc] += m ? v  : 0.0f;
            a2[cc] += m ? v2 : 0.0f;
        }
    }
#pragma unroll
    for (int cc = 0; cc < NCLS; cc++) {
        red1[g][cc * NDIM + k] = a1[cc];
        red2[g][cc * NDIM + k] = a2[cc];
    }
    __syncthreads();
#pragma unroll
    for (int q = 0; q < 2; q++) {
        int idx = q * 256 + t;
        float s1 = red1[0][idx] + red1[1][idx] + red1[2][idx] + red1[3][idx];
        float s2 = red2[0][idx] + red2[1][idx] + red2[2][idx] + red2[3][idx];
        atomicAdd(&g_s1[idx], s1);
        atomicAdd(&g_s2[idx], s2);
    }
    if (t < NCLS) {
        int cnt = 0;
#pragma unroll
        for (int rr = 0; rr < 64; rr++) cnt += (slab[rr] == t) ? 1 : 0;
        atomicAdd(&g_hist[t], cnt);
    }
}

// ---------------- rare path: exact 64-dim evaluation ----------------
__device__ __noinline__ void eval_pair(const float* __restrict__ X,
                                       const int* __restrict__ lab, int i, int j) {
    if (j <= i) return;
    if (lab[i] == lab[j]) return;       // same-label handled in closed form
    const float4* xi = (const float4*)(X + i * NDIM);
    const float4* xj = (const float4*)(X + j * NDIM);
    float s = 0.0f;
#pragma unroll
    for (int q = 0; q < 16; q++) {
        float4 a = xi[q], b = xj[q];
        float d;
        d = a.x - b.x; s = fmaf(d, d, s);
        d = a.y - b.y; s = fmaf(d, d, s);
        d = a.z - b.z; s = fmaf(d, d, s);
        d = a.w - b.w; s = fmaf(d, d, s);
    }
    if (s < 1.0f) {
        float u = 1.0f - sqrtf(fmaxf(s, 0.0f));
        atomicAdd(&g_neg, 2.0 * (double)u * (double)u);   // unordered -> ordered pairs
    }
}

__device__ __forceinline__ float half_norm8(float4 v0, float4 v1) {
    float s = v0.x * v0.x;
    s = fmaf(v0.y, v0.y, s);
    s = fmaf(v0.z, v0.z, s);
    s = fmaf(v0.w, v0.w, s);
    s = fmaf(v1.x, v1.x, s);
    s = fmaf(v1.y, v1.y, s);
    s = fmaf(v1.z, v1.z, s);
    s = fmaf(v1.w, v1.w, s);
    return 0.5f * s;
}

// ---------------- K2: screen (8-dim dot-form lower bound) + compaction --------
// grid (64, 16), 128 threads. Block (bj,bi): i in [bi*512,+512), j in [bj*128,+128).
// Keep blocks that can contain j > i pairs: bj >= 4*bi.
// Pass test: dot8 - hj > hi - 0.505  <=>  partial d2 over 8 dims < 1.01 (exact LB).
__global__ void __launch_bounds__(128) screen_kernel(const float* __restrict__ X,
                                                     const int* __restrict__ lab) {
    int bi = blockIdx.y, bj = blockIdx.x;
    if (bj < 4 * bi) return;
    int t = threadIdx.x;

    __shared__ float4   sj[TJ][2];
    __shared__ float    smhj[TJ];       // -hj
    __shared__ unsigned sbuf[SCAP];
    __shared__ int      scnt;
    const float4* Xv = (const float4*)X;

    if (t == 0) scnt = 0;
    int jr = bj * TJ + t;
    float4 j0 = Xv[jr * 16 + 0];
    float4 j1 = Xv[jr * 16 + 1];
    sj[t][0] = j0;
    sj[t][1] = j1;
    smhj[t]  = -half_norm8(j0, j1);

    float4 a[4][2];
    float  ci[4];
    int    ib[4];
#pragma unroll
    for (int r = 0; r < 4; r++) {
        ib[r]   = bi * TI + r * 128 + t;
        a[r][0] = Xv[ib[r] * 16 + 0];
        a[r][1] = Xv[ib[r] * 16 + 1];
        ci[r]   = half_norm8(a[r][0], a[r][1]) - 0.505f;
    }
    __syncthreads();

    bool diag = (bj < 4 * bi + 4);
    if (!diag) {
#pragma unroll 4
        for (int j = 0; j < TJ; ++j) {
            float4 b0 = sj[j][0];
            float4 b1 = sj[j][1];
            float mhj = smhj[j];
#pragma unroll
            for (int r = 0; r < 4; r++) {
                float dot = fmaf(a[r][0].x, b0.x, mhj);
                dot = fmaf(a[r][0].y, b0.y, dot);
                dot = fmaf(a[r][0].z, b0.z, dot);
                dot = fmaf(a[r][0].w, b0.w, dot);
                dot = fmaf(a[r][1].x, b1.x, dot);
                dot = fmaf(a[r][1].y, b1.y, dot);
                dot = fmaf(a[r][1].z, b1.z, dot);
                dot = fmaf(a[r][1].w, b1.w, dot);
                if (dot > ci[r]) {
                    int idx = atomicAdd(&scnt, 1);
                    if (idx < SCAP)
                        sbuf[idx] = ((unsigned)ib[r] << 13) | (unsigned)(bj * TJ + j);
                }
            }
        }
    } else {
#pragma unroll 4
        for (int j = 0; j < TJ; ++j) {
            float4 b0 = sj[j][0];
            float4 b1 = sj[j][1];
            float mhj = smhj[j];
            int    jg = bj * TJ + j;
#pragma unroll
            for (int r = 0; r < 4; r++) {
                float dot = fmaf(a[r][0].x, b0.x, mhj);
                dot = fmaf(a[r][0].y, b0.y, dot);
                dot = fmaf(a[r][0].z, b0.z, dot);
                dot = fmaf(a[r][0].w, b0.w, dot);
                dot = fmaf(a[r][1].x, b1.x, dot);
                dot = fmaf(a[r][1].y, b1.y, dot);
                dot = fmaf(a[r][1].z, b1.z, dot);
                dot = fmaf(a[r][1].w, b1.w, dot);
                if (dot > ci[r] && jg > ib[r]) {
                    int idx = atomicAdd(&scnt, 1);
                    if (idx < SCAP)
                        sbuf[idx] = ((unsigned)ib[r] << 13) | (unsigned)jg;
                }
            }
        }
    }
    __syncthreads();

    if (scnt <= SCAP) {
        // normal path: evaluate compacted survivors cooperatively
        for (int q = t; q < scnt; q += 128) {
            unsigned e = sbuf[q];
            eval_pair(X, lab, (int)(e >> 13), (int)(e & 8191u));
        }
    } else {
        // overflow (rare; correctness guard): discard buffer, re-screen this
        // tile with direct evaluation of every passing pair.
#pragma unroll 1
        for (int j = 0; j < TJ; ++j) {
            float4 b0 = sj[j][0];
            float4 b1 = sj[j][1];
            float mhj = smhj[j];
            int    jg = bj * TJ + j;
#pragma unroll 1
            for (int r = 0; r < 4; r++) {
                float dot = fmaf(a[r][0].x, b0.x, mhj);
                dot = fmaf(a[r][0].y, b0.y, dot);
                dot = fmaf(a[r][0].z, b0.z, dot);
                dot = fmaf(a[r][0].w, b0.w, dot);
                dot = fmaf(a[r][1].x, b1.x, dot);
                dot = fmaf(a[r][1].y, b1.y, dot);
                dot = fmaf(a[r][1].z, b1.z, dot);
                dot = fmaf(a[r][1].w, b1.w, dot);
                if (dot > ci[r] && jg > ib[r]) eval_pair(X, lab, ib[r], jg);
            }
        }
    }
}

// ---------------- K3: finalize (tiny) + reset accumulators --------------------
__global__ void __launch_bounds__(512) finalize_kernel(float* __restrict__ out) {
    int t = threadIdx.x;                    // t = c*64 + k
    __shared__ double red[512];

    int c = t >> 6;
    double S1 = (double)g_s1[t];
    double S2 = (double)g_s2[t];
    red[t] = (double)g_hist[c] * S2 - S1 * S1;
    __syncthreads();
    for (int s = 256; s > 0; s >>= 1) {
        if (t < s) red[t] += red[t + s];
        __syncthreads();
    }
    if (t == 0) {
        double pos  = 2.0 * red[0];
        double loss = (pos + g_neg) / ((double)N_PTS * (double)(N_PTS - 1));
        out[0] = (float)loss;
    }
    // reset for the next graph replay (globals are 0 at module load)
    g_s1[t] = 0.0f;
    g_s2[t] = 0.0f;
    if (t < NCLS) g_hist[t] = 0;
    if (t == 0)   g_neg = 0.0;
}

extern "C" void kernel_launch(void* const* d_in, const int* in_sizes, int n_in,
                              void* d_out, int out_size) {
    const float* X   = (const float*)d_in[0];
    const int*   lab = (const int*)d_in[1];
    float*       out = (float*)d_out;

    prep_kernel<<<128, 256>>>(X, lab);
    dim3 g(64, 16);
    screen_kernel<<<g, 128>>>(X, lab);
    finalize_kernel<<<1, 512>>>(out);
}